// round 16
// baseline (speedup 1.0000x reference)
#include <cuda_runtime.h>
#include <cstdint>

#define T_LEN 4096
#define E_DIM 256
#define H_DIM 256
#define G_DIM 1024   // 4*H
#define L_TAGS 18
#define START_TAG 16
#define STOP_TAG 17
#define NEGV (-10000.0f)

// ---------------- device scratch (static: no allocations allowed) ----------
__device__ float g_pre[2][(size_t)T_LEN * G_DIM];   // pre-activations, fwd/bwd
__device__ float g_h[2][(size_t)T_LEN * H_DIM];     // hf / hb
__device__ float g_emit[(size_t)T_LEN * L_TAGS];    // emissions

// ---------------- small helpers -------------------------------------------
__device__ __forceinline__ unsigned long long ffma2(unsigned long long a,
                                                    unsigned long long b,
                                                    unsigned long long c) {
    unsigned long long d;
    asm("fma.rn.f32x2 %0, %1, %2, %3;" : "=l"(d) : "l"(a), "l"(b), "l"(c));
    return d;
}
__device__ __forceinline__ float2 unpackf2(unsigned long long v) {
    float2 r;
    asm("mov.b64 {%0, %1}, %2;" : "=f"(r.x), "=f"(r.y) : "l"(v));
    return r;
}
__device__ __forceinline__ float sigmoidf_(float x) {
    return __fdividef(1.0f, 1.0f + __expf(-x));
}
__device__ __forceinline__ float tanh_fast(float x) {
    float e = __expf(2.0f * x);
    return 1.0f - __fdividef(2.0f, e + 1.0f);
}
__device__ __forceinline__ uint32_t smem_u32(const void* p) {
    uint32_t a;
    asm("{ .reg .u64 t; cvta.to.shared.u64 t, %1; cvt.u32.u64 %0, t; }"
        : "=r"(a) : "l"(p));
    return a;
}
__device__ __forceinline__ uint32_t mapa_u32(uint32_t local, uint32_t rank) {
    uint32_t r;
    asm("mapa.shared::cluster.u32 %0, %1, %2;" : "=r"(r) : "r"(local), "r"(rank));
    return r;
}
__device__ __forceinline__ void mbar_init(uint32_t mbar, uint32_t count) {
    asm volatile("mbarrier.init.shared::cta.b64 [%0], %1;" :: "r"(mbar), "r"(count)
                 : "memory");
}
__device__ __forceinline__ void mbar_expect_tx(uint32_t mbar, uint32_t bytes) {
    asm volatile("mbarrier.arrive.expect_tx.shared::cta.b64 _, [%0], %1;"
                 :: "r"(mbar), "r"(bytes) : "memory");
}
// spin-then-sleep wait: one fast-path try_wait, then HW-sleep hinted loop.
__device__ __forceinline__ void mbar_wait(uint32_t mbar, uint32_t parity) {
    uint32_t done;
    asm volatile(
        "{\n\t.reg .pred P;\n\t"
        "mbarrier.try_wait.parity.acquire.cta.shared::cta.b64 P, [%1], %2;\n\t"
        "selp.b32 %0, 1, 0, P;\n\t}"
        : "=r"(done) : "r"(mbar), "r"(parity) : "memory");
    if (!done) {
        asm volatile(
            "{\n\t.reg .pred P;\n\t"
            "W_%=:\n\t"
            "mbarrier.try_wait.parity.acquire.cta.shared::cta.b64 P, [%0], %1, 0x989680;\n\t"
            "@P bra.uni D_%=;\n\t"
            "bra.uni W_%=;\n\t"
            "D_%=:\n\t}"
            :: "r"(mbar), "r"(parity) : "memory");
    }
}
// one-shot 128B SMEM -> remote-CTA SMEM with single tx update on remote mbar
__device__ __forceinline__ void bulk_s2cluster(uint32_t dst, uint32_t src,
                                               uint32_t bytes, uint32_t rmbar) {
    asm volatile(
        "cp.async.bulk.shared::cluster.shared::cta.mbarrier::complete_tx::bytes "
        "[%0], [%1], %2, [%3];"
        :: "r"(dst), "r"(src), "r"(bytes), "r"(rmbar) : "memory");
}
__device__ __forceinline__ void cp_async16(uint32_t dst, const void* src) {
    asm volatile("cp.async.ca.shared.global [%0], [%1], 16;"
                 :: "r"(dst), "l"(src) : "memory");
}

// ---------------- 1) fused gather + input GEMM -----------------------------
__global__ __launch_bounds__(256) void gemm_pre_kernel(
    const int* __restrict__ feats, const float* __restrict__ emb,
    const float* __restrict__ wih_f, const float* __restrict__ wih_b,
    const float* __restrict__ b_f, const float* __restrict__ b_b) {
    int dir = blockIdx.z;
    const float* wih  = dir ? wih_b : wih_f;
    const float* bias = dir ? b_b : b_f;
    float* out = g_pre[dir];

    int m0 = blockIdx.y * 64;
    int n0 = blockIdx.x * 64;

    __shared__ __align__(16) float As[64][68];
    __shared__ __align__(16) float Bs[64][68];
    __shared__ int fid[64];

    int tid = threadIdx.x;
    int tx = tid & 15, ty = tid >> 4;

    if (tid < 64) fid[tid] = feats[m0 + tid];
    __syncthreads();

    float acc[4][4];
#pragma unroll
    for (int i = 0; i < 4; i++)
#pragma unroll
        for (int j = 0; j < 4; j++) acc[i][j] = 0.f;

    for (int kb = 0; kb < 4; kb++) {
#pragma unroll
        for (int i = 0; i < 16; i++) {
            int idx = tid + i * 256;
            int m = idx >> 6, k = idx & 63;
            As[k][m] = emb[(size_t)fid[m] * E_DIM + kb * 64 + k];
            Bs[k][m] = wih[(size_t)(n0 + m) * E_DIM + kb * 64 + k];
        }
        __syncthreads();
#pragma unroll
        for (int k = 0; k < 64; k++) {
            float4 a4 = *(const float4*)&As[k][ty * 4];
            float4 b4 = *(const float4*)&Bs[k][tx * 4];
            float av[4] = {a4.x, a4.y, a4.z, a4.w};
            float bv[4] = {b4.x, b4.y, b4.z, b4.w};
#pragma unroll
            for (int i = 0; i < 4; i++)
#pragma unroll
                for (int j = 0; j < 4; j++) acc[i][j] += av[i] * bv[j];
        }
        __syncthreads();
    }
#pragma unroll
    for (int j = 0; j < 4; j++) {
        float bj = bias[n0 + tx * 4 + j];
#pragma unroll
        for (int i = 0; i < 4; i++)
            out[(size_t)(m0 + ty * 4 + i) * G_DIM + n0 + tx * 4 + j] =
                acc[i][j] + bj;
    }
}

// ---------------- 2) LSTM recurrence: 4-CTA cluster, 512 threads -----------
// Same per-thread tile and comm mechanism as R9, but 64 units/CTA:
//  - straggler set per step: max over 4 CTAs instead of 8
//  - 6 outgoing 128B bulks (2 halves x 3 peers), 6 incoming tx RMWs
__global__ void __cluster_dims__(4, 1, 1) __launch_bounds__(512, 1)
lstm_cluster_kernel(const float* __restrict__ whh_f,
                    const float* __restrict__ whh_b) {
    __shared__ __align__(16) float hsm[2][288];        // 36-stride padded h
    __shared__ __align__(16) float pre_s[3][16][288];  // 16 steps x 4x72
    __shared__ __align__(16) float hstage[2][64];      // fresh h, dbl-buffered
    __shared__ __align__(8) unsigned long long mbar_sm[2];

    uint32_t rank;
    asm("mov.u32 %0, %%cluster_ctarank;" : "=r"(rank));
    int dir = blockIdx.x >> 2;

    const float* whh = dir ? whh_b : whh_f;
    const float* pre = g_pre[dir];
    float* hout = g_h[dir];

    int tid = threadIdx.x;
    int lane = tid & 31, warp = tid >> 5;       // 16 warps
    int cb = lane & 7;                          // column block [32cb,32cb+32)
    int ub = lane >> 3;                         // unit within warp (0..3)
    int unit = warp * 4 + ub;                   // local unit 0..63
    int k_unit = (int)rank * 64 + unit;         // global hidden unit

    // weights: all 4 gates of this unit, 32 cols -> 128 floats = 64 f32x2
    unsigned long long wr[4][16];
#pragma unroll
    for (int gg = 0; gg < 4; gg++) {
        const ulonglong2* wp = (const ulonglong2*)(
            whh + (size_t)(gg * 256 + k_unit) * H_DIM + cb * 32);
#pragma unroll
        for (int q = 0; q < 8; q++) {
            ulonglong2 v = wp[q];
            wr[gg][2 * q] = v.x;
            wr[gg][2 * q + 1] = v.y;
        }
    }

    for (int i = tid; i < 288; i += 512) { hsm[0][i] = 0.f; hsm[1][i] = 0.f; }

    uint32_t hbase = smem_u32(&hsm[0][0]);
    uint32_t pbase = smem_u32(&pre_s[0][0][0]);
    uint32_t sbase = smem_u32(&hstage[0][0]);
    uint32_t mb0 = smem_u32(&mbar_sm[0]);
    uint32_t mb1 = smem_u32(&mbar_sm[1]);

    if (tid == 0) {
        mbar_init(mb0, 1);
        mbar_init(mb1, 1);
        mbar_expect_tx(mb1, 768);    // step-0 sends (3 peers x 2 x 128B)
    }

    // pre loader: per chunk 16 steps x 256 floats = 1024 x 16B pieces;
    // 512 threads x 2 pieces. idx: si = idx>>6, gate = (idx&63)>>4, l16 = idx&15
#define PRE_ISSUE(ck, ring)                                                   \
    do {                                                                      \
        _Pragma("unroll")                                                     \
        for (int pp = 0; pp < 2; pp++) {                                      \
            int idx = tid + pp * 512;                                         \
            int si_ = idx >> 6;                                               \
            int ga_ = (idx & 63) >> 4, l16_ = idx & 15;                       \
            int ss_ = (ck) * 16 + si_;                                        \
            int tt_ = dir ? (T_LEN - 1 - ss_) : ss_;                          \
            const float* src_ = pre + (size_t)tt_ * G_DIM + ga_ * 256 +       \
                                (int)rank * 64 + l16_ * 4;                    \
            uint32_t dst_ = pbase +                                           \
                (uint32_t)(((ring) * 16 + si_) * 288 + ga_ * 72 +             \
                           l16_ * 4) * 4u;                                    \
            cp_async16(dst_, src_);                                           \
        }                                                                     \
        asm volatile("cp.async.commit_group;" ::: "memory");                  \
    } while (0)

    PRE_ISSUE(0, 0);
    PRE_ISSUE(1, 1);

    // sender setup (warp 0 lanes 0-7): peer = lane>>1, half = lane&1;
    // skip self. This CTA's 64 h occupy padded blocks 2*rank, 2*rank+1 =
    // float offsets 72*rank + 36*half in every CTA's hsm buffer.
    int peer = lane >> 1, half = lane & 1;
    bool sender = (warp == 0 && lane < 8 && (uint32_t)peer != rank);
    uint32_t dst_b0 = 0, dst_b1 = 0, mdst0 = 0, mdst1 = 0;
    if (warp == 0 && lane < 8) {
        uint32_t foff = (uint32_t)(72 * (int)rank + 36 * half);
        dst_b0 = mapa_u32(hbase + foff * 4u, (uint32_t)peer);
        dst_b1 = mapa_u32(hbase + (288u + foff) * 4u, (uint32_t)peer);
        mdst0 = mapa_u32(mb0, (uint32_t)peer);
        mdst1 = mapa_u32(mb1, (uint32_t)peer);
    }

    __syncthreads();
    asm volatile("barrier.cluster.arrive.aligned;" ::: "memory");
    asm volatile("barrier.cluster.wait.aligned;" ::: "memory");

    float c = 0.f;                 // cell state at cb==0 lanes
    uint32_t par0 = 0, par1 = 0;

    for (int s = 0; s < T_LEN; s++) {
        int b = s & 1;
        int si = s & 15;
        int t = dir ? (T_LEN - 1 - s) : s;

        if (si == 0) {
            int c2 = (s >> 4) + 2;
            if (c2 < (T_LEN / 16)) {
                PRE_ISSUE(c2, c2 % 3);
                asm volatile("cp.async.wait_group 2;" ::: "memory");
            } else {
                asm volatile("cp.async.wait_group 0;" ::: "memory");
            }
            __syncthreads();
        }
        int buf = (s >> 4) % 3;

        // pre for gate cb of this unit (only cb<4 lanes add it)
        float p = (cb < 4) ? pre_s[buf][si][cb * 72 + unit] : 0.f;

        // wait until all 3 remote CTAs delivered h for this step
        if (s > 0) {
            if (b) { mbar_wait(mb1, par1); par1 ^= 1; }
            else   { mbar_wait(mb0, par0); par0 ^= 1; }
        }
        if (tid == 0) mbar_expect_tx(b ? mb1 : mb0, 768);

        // matvec: 4 gate rows x 32 cols; h from hsm[b] block cb
        const ulonglong2* h2 = (const ulonglong2*)(&hsm[b][cb * 36]);
        unsigned long long a0 = 0ull, a1 = 0ull, a2 = 0ull, a3 = 0ull;
#pragma unroll
        for (int q = 0; q < 8; q++) {
            ulonglong2 hv = h2[q];
            a0 = ffma2(wr[0][2 * q], hv.x, a0);
            a1 = ffma2(wr[1][2 * q], hv.x, a1);
            a2 = ffma2(wr[2][2 * q], hv.x, a2);
            a3 = ffma2(wr[3][2 * q], hv.x, a3);
            a0 = ffma2(wr[0][2 * q + 1], hv.y, a0);
            a1 = ffma2(wr[1][2 * q + 1], hv.y, a1);
            a2 = ffma2(wr[2][2 * q + 1], hv.y, a2);
            a3 = ffma2(wr[3][2 * q + 1], hv.y, a3);
        }
        float2 f0 = unpackf2(a0), f1 = unpackf2(a1);
        float2 f2 = unpackf2(a2), f3 = unpackf2(a3);
        float s0 = f0.x + f0.y, s1 = f1.x + f1.y;
        float s2 = f2.x + f2.y, s3 = f3.x + f3.y;

        if (cb == 0) s0 += p;
        else if (cb == 1) s1 += p;
        else if (cb == 2) s2 += p;
        else if (cb == 3) s3 += p;

#pragma unroll
        for (int mk = 1; mk < 8; mk <<= 1) {
            s0 += __shfl_xor_sync(0xffffffffu, s0, mk);
            s1 += __shfl_xor_sync(0xffffffffu, s1, mk);
            s2 += __shfl_xor_sync(0xffffffffu, s2, mk);
            s3 += __shfl_xor_sync(0xffffffffu, s3, mk);
        }

        // gates at cb==0 lanes (4 per warp), one unit each
        if (cb == 0) {
            float ii = sigmoidf_(s0);
            float ff = sigmoidf_(s1);
            float oo = sigmoidf_(s3);
            c = ff * c + ii * tanh_fast(s2);
            float h = oo * tanh_fast(c);
            hstage[b ^ 1][unit] = h;
            hsm[b ^ 1][36 * (2 * (int)rank + (unit >> 5)) + (unit & 31)] = h;
            hout[(size_t)t * H_DIM + k_unit] = h;    // off critical path
        }
        __syncthreads();   // hstage + local hsm staged; hsm[b] reads retired

        // warp 0: 6 bulk sends (2 halves x 3 peers), one tx RMW each
        if (sender) {
            asm volatile("fence.proxy.async.shared::cta;" ::: "memory");
            uint32_t d = b ? dst_b0 : dst_b1;   // step-s output -> buffer b^1
            uint32_t m = b ? mdst0 : mdst1;
            uint32_t ssrc = sbase + (uint32_t)((b ^ 1) * 64 + 32 * half) * 4u;
            bulk_s2cluster(d, ssrc, 128u, m);
        }
    }

    // drain: final sends (step T-1, odd) targeted mb0; complete that phase
    mbar_wait(mb0, par0);
    asm volatile("barrier.cluster.arrive.aligned;" ::: "memory");
    asm volatile("barrier.cluster.wait.aligned;" ::: "memory");
#undef PRE_ISSUE
}

// ---------------- 3) emit: 16 timesteps per block, W_out SMEM-cached -------
__global__ __launch_bounds__(128) void emit_kernel(
    const float* __restrict__ Wout, const float* __restrict__ bout) {
    int t0 = blockIdx.x * 16;
    __shared__ float Wsm[L_TAGS * 512];     // 36 KB
    __shared__ float h[512];
    __shared__ float part[4][18];
    int tid = threadIdx.x;

    for (int i = tid; i < L_TAGS * 512; i += 128) Wsm[i] = Wout[i];

    for (int tl = 0; tl < 16; tl++) {
        int t = t0 + tl;
        __syncthreads();            // also covers Wsm on first iteration
        h[tid]       = g_h[0][(size_t)t * 256 + tid];
        h[tid + 128] = g_h[0][(size_t)t * 256 + 128 + tid];
        h[tid + 256] = g_h[1][(size_t)t * 256 + tid];
        h[tid + 384] = g_h[1][(size_t)t * 256 + 128 + tid];
        __syncthreads();

        if (tid < 72) {
            int jj = tid >> 2, q = tid & 3;
            const float* w = Wsm + jj * 512 + q * 128;
            const float* hh = h + q * 128;
            float a0 = 0.f, a1 = 0.f, a2 = 0.f, a3 = 0.f;
#pragma unroll
            for (int k = 0; k < 128; k += 4) {
                a0 += hh[k] * w[k];
                a1 += hh[k + 1] * w[k + 1];
                a2 += hh[k + 2] * w[k + 2];
                a3 += hh[k + 3] * w[k + 3];
            }
            part[q][jj] = (a0 + a1) + (a2 + a3);
        }
        __syncthreads();
        if (tid < 18)
            g_emit[(size_t)t * L_TAGS + tid] =
                part[0][tid] + part[1][tid] + part[2][tid] + part[3][tid] +
                bout[tid];
    }
}

// ---------------- 4) Viterbi + backtrack (one warp, R9 variant) -------------
__global__ void viterbi_kernel(const float* __restrict__ trans,
                               float* __restrict__ out, int write_score) {
    extern __shared__ unsigned char bp[];
    int j = threadIdx.x;
    bool act = (j < L_TAGS);

    float tcol[L_TAGS];
#pragma unroll
    for (int i = 0; i < L_TAGS; i++)
        tcol[i] = act ? trans[i * L_TAGS + j] : 0.f;

    float fv = act ? ((j == START_TAG) ? 0.f : NEGV) : -3.0e38f;
    float e = act ? g_emit[j] : 0.f;

    for (int t = 0; t < T_LEN; t++) {
        float e_next = (act && t + 1 < T_LEN)
                           ? g_emit[(size_t)(t + 1) * L_TAGS + j] : 0.f;
        // 3 independent chains of 6, merged ascending with strict >
        float b0 = -3.4e38f, b1 = -3.4e38f, b2 = -3.4e38f;
        int a0 = 0, a1 = 6, a2 = 12;
#pragma unroll
        for (int i = 0; i < 6; i++) {
            float s0 = __shfl_sync(0xffffffffu, fv, i) + tcol[i];
            float s1 = __shfl_sync(0xffffffffu, fv, i + 6) + tcol[i + 6];
            float s2 = __shfl_sync(0xffffffffu, fv, i + 12) + tcol[i + 12];
            if (s0 > b0) { b0 = s0; a0 = i; }
            if (s1 > b1) { b1 = s1; a1 = i + 6; }
            if (s2 > b2) { b2 = s2; a2 = i + 12; }
        }
        float best = b0; int arg = a0;
        if (b1 > best) { best = b1; arg = a1; }
        if (b2 > best) { best = b2; arg = a2; }

        if (act) {
            bp[t * L_TAGS + j] = (unsigned char)arg;
            fv = best + e;
        }
        e = e_next;
    }

    float term = act ? (fv + trans[j * L_TAGS + STOP_TAG]) : -3.4e38f;
    int ai = j;
#pragma unroll
    for (int off = 16; off > 0; off >>= 1) {
        float ov = __shfl_xor_sync(0xffffffffu, term, off);
        int oi = __shfl_xor_sync(0xffffffffu, ai, off);
        if (ov > term || (ov == term && oi < ai)) { term = ov; ai = oi; }
    }

    if (j == 0) {
        if (write_score) out[0] = term;
        float* path = out + write_score;
        int tag = ai;
        for (int t = T_LEN - 1; t >= 0; t--) {
            path[t] = (float)tag;
            tag = bp[t * L_TAGS + tag];
        }
    }
}

// ---------------- launch ----------------------------------------------------
extern "C" void kernel_launch(void* const* d_in, const int* in_sizes, int n_in,
                              void* d_out, int out_size) {
    const int*   feats  = (const int*)d_in[0];
    const float* emb    = (const float*)d_in[1];
    const float* w_ih_f = (const float*)d_in[2];
    const float* w_hh_f = (const float*)d_in[3];
    const float* b_f    = (const float*)d_in[4];
    const float* w_ih_b = (const float*)d_in[5];
    const float* w_hh_b = (const float*)d_in[6];
    const float* b_b    = (const float*)d_in[7];
    const float* W_out  = (const float*)d_in[8];
    const float* b_out  = (const float*)d_in[9];
    const float* trans  = (const float*)d_in[10];

    dim3 gg(G_DIM / 64, T_LEN / 64, 2);
    gemm_pre_kernel<<<gg, 256>>>(feats, emb, w_ih_f, w_ih_b, b_f, b_b);

    // 2 clusters x 4 CTAs x 512 threads
    lstm_cluster_kernel<<<8, 512>>>(w_hh_f, w_hh_b);

    emit_kernel<<<T_LEN / 16, 128>>>(W_out, b_out);

    int ws = (out_size > T_LEN) ? 1 : 0;   // layout: [path_score, path...]
    static int smem_set = 0;
    if (!smem_set) {
        cudaFuncSetAttribute(viterbi_kernel,
                             cudaFuncAttributeMaxDynamicSharedMemorySize,
                             T_LEN * L_TAGS + 1024);
        smem_set = 1;
    }
    viterbi_kernel<<<1, 32, T_LEN * L_TAGS>>>(trans, (float*)d_out, ws);
}

// round 17
// speedup vs baseline: 1.9123x; 1.9123x over previous
#include <cuda_runtime.h>
#include <cstdint>

#define T_LEN 4096
#define E_DIM 256
#define H_DIM 256
#define G_DIM 1024   // 4*H
#define L_TAGS 18
#define START_TAG 16
#define STOP_TAG 17
#define NEGV (-10000.0f)

// ---------------- device scratch (static: no allocations allowed) ----------
__device__ float g_pre[2][(size_t)T_LEN * G_DIM];   // pre-activations, fwd/bwd
__device__ float g_h[2][(size_t)T_LEN * H_DIM];     // hf / hb
__device__ float g_emit[(size_t)T_LEN * L_TAGS];    // emissions

// ---------------- small helpers -------------------------------------------
__device__ __forceinline__ unsigned long long ffma2(unsigned long long a,
                                                    unsigned long long b,
                                                    unsigned long long c) {
    unsigned long long d;
    asm("fma.rn.f32x2 %0, %1, %2, %3;" : "=l"(d) : "l"(a), "l"(b), "l"(c));
    return d;
}
__device__ __forceinline__ float2 unpackf2(unsigned long long v) {
    float2 r;
    asm("mov.b64 {%0, %1}, %2;" : "=f"(r.x), "=f"(r.y) : "l"(v));
    return r;
}
__device__ __forceinline__ float sigmoidf_(float x) {
    return __fdividef(1.0f, 1.0f + __expf(-x));
}
__device__ __forceinline__ float tanh_fast(float x) {
    float e = __expf(2.0f * x);
    return 1.0f - __fdividef(2.0f, e + 1.0f);
}
__device__ __forceinline__ uint32_t smem_u32(const void* p) {
    uint32_t a;
    asm("{ .reg .u64 t; cvta.to.shared.u64 t, %1; cvt.u32.u64 %0, t; }"
        : "=r"(a) : "l"(p));
    return a;
}
__device__ __forceinline__ uint32_t mapa_u32(uint32_t local, uint32_t rank) {
    uint32_t r;
    asm("mapa.shared::cluster.u32 %0, %1, %2;" : "=r"(r) : "r"(local), "r"(rank));
    return r;
}
__device__ __forceinline__ void mbar_init(uint32_t mbar, uint32_t count) {
    asm volatile("mbarrier.init.shared::cta.b64 [%0], %1;" :: "r"(mbar), "r"(count)
                 : "memory");
}
__device__ __forceinline__ void mbar_expect_tx(uint32_t mbar, uint32_t bytes) {
    asm volatile("mbarrier.arrive.expect_tx.shared::cta.b64 _, [%0], %1;"
                 :: "r"(mbar), "r"(bytes) : "memory");
}
// spin-then-sleep wait: one fast-path try_wait, then HW-sleep hinted loop.
__device__ __forceinline__ void mbar_wait(uint32_t mbar, uint32_t parity) {
    uint32_t done;
    asm volatile(
        "{\n\t.reg .pred P;\n\t"
        "mbarrier.try_wait.parity.acquire.cta.shared::cta.b64 P, [%1], %2;\n\t"
        "selp.b32 %0, 1, 0, P;\n\t}"
        : "=r"(done) : "r"(mbar), "r"(parity) : "memory");
    if (!done) {
        asm volatile(
            "{\n\t.reg .pred P;\n\t"
            "W_%=:\n\t"
            "mbarrier.try_wait.parity.acquire.cta.shared::cta.b64 P, [%0], %1, 0x989680;\n\t"
            "@P bra.uni D_%=;\n\t"
            "bra.uni W_%=;\n\t"
            "D_%=:\n\t}"
            :: "r"(mbar), "r"(parity) : "memory");
    }
}
// one-shot 128B SMEM -> remote-CTA SMEM with single tx update on remote mbar
__device__ __forceinline__ void bulk_s2cluster(uint32_t dst, uint32_t src,
                                               uint32_t bytes, uint32_t rmbar) {
    asm volatile(
        "cp.async.bulk.shared::cluster.shared::cta.mbarrier::complete_tx::bytes "
        "[%0], [%1], %2, [%3];"
        :: "r"(dst), "r"(src), "r"(bytes), "r"(rmbar) : "memory");
}
__device__ __forceinline__ void cp_async16(uint32_t dst, const void* src) {
    asm volatile("cp.async.ca.shared.global [%0], [%1], 16;"
                 :: "r"(dst), "l"(src) : "memory");
}

// ---------------- 1) fused gather + input GEMM -----------------------------
__global__ __launch_bounds__(256) void gemm_pre_kernel(
    const int* __restrict__ feats, const float* __restrict__ emb,
    const float* __restrict__ wih_f, const float* __restrict__ wih_b,
    const float* __restrict__ b_f, const float* __restrict__ b_b) {
    int dir = blockIdx.z;
    const float* wih  = dir ? wih_b : wih_f;
    const float* bias = dir ? b_b : b_f;
    float* out = g_pre[dir];

    int m0 = blockIdx.y * 64;
    int n0 = blockIdx.x * 64;

    __shared__ __align__(16) float As[64][68];
    __shared__ __align__(16) float Bs[64][68];
    __shared__ int fid[64];

    int tid = threadIdx.x;
    int tx = tid & 15, ty = tid >> 4;

    if (tid < 64) fid[tid] = feats[m0 + tid];
    __syncthreads();

    float acc[4][4];
#pragma unroll
    for (int i = 0; i < 4; i++)
#pragma unroll
        for (int j = 0; j < 4; j++) acc[i][j] = 0.f;

    for (int kb = 0; kb < 4; kb++) {
#pragma unroll
        for (int i = 0; i < 16; i++) {
            int idx = tid + i * 256;
            int m = idx >> 6, k = idx & 63;
            As[k][m] = emb[(size_t)fid[m] * E_DIM + kb * 64 + k];
            Bs[k][m] = wih[(size_t)(n0 + m) * E_DIM + kb * 64 + k];
        }
        __syncthreads();
#pragma unroll
        for (int k = 0; k < 64; k++) {
            float4 a4 = *(const float4*)&As[k][ty * 4];
            float4 b4 = *(const float4*)&Bs[k][tx * 4];
            float av[4] = {a4.x, a4.y, a4.z, a4.w};
            float bv[4] = {b4.x, b4.y, b4.z, b4.w};
#pragma unroll
            for (int i = 0; i < 4; i++)
#pragma unroll
                for (int j = 0; j < 4; j++) acc[i][j] += av[i] * bv[j];
        }
        __syncthreads();
    }
#pragma unroll
    for (int j = 0; j < 4; j++) {
        float bj = bias[n0 + tx * 4 + j];
#pragma unroll
        for (int i = 0; i < 4; i++)
            out[(size_t)(m0 + ty * 4 + i) * G_DIM + n0 + tx * 4 + j] =
                acc[i][j] + bj;
    }
}

// ---------------- 2) LSTM recurrence: R9 exactly (validated optimum) -------
// Only deviation from R9: the hout global store is issued AFTER the sender
// block (off the pre-barrier critical path), from register.
__global__ void __cluster_dims__(8, 1, 1) __launch_bounds__(256, 1)
lstm_cluster_kernel(const float* __restrict__ whh_f,
                    const float* __restrict__ whh_b) {
    __shared__ __align__(16) float hsm[2][288];        // 36-stride padded h
    __shared__ __align__(16) float pre_s[3][16][144];  // 16 steps x 4x36
    __shared__ __align__(16) float hstage[2][32];      // fresh h, dbl-buffered
    __shared__ __align__(8) unsigned long long mbar_sm[2];

    uint32_t rank;
    asm("mov.u32 %0, %%cluster_ctarank;" : "=r"(rank));
    int dir = blockIdx.x >> 3;

    const float* whh = dir ? whh_b : whh_f;
    const float* pre = g_pre[dir];
    float* hout = g_h[dir];

    int tid = threadIdx.x;
    int lane = tid & 31, warp = tid >> 5;       // 8 warps
    int cb = lane & 7;                          // column block [32cb,32cb+32)
    int ub = lane >> 3;                         // unit within warp (0..3)
    int unit = warp * 4 + ub;                   // local unit 0..31
    int k_unit = (int)rank * 32 + unit;         // global hidden unit

    // weights: all 4 gates of this unit, 32 cols -> 128 floats = 64 f32x2
    unsigned long long wr[4][16];
#pragma unroll
    for (int gg = 0; gg < 4; gg++) {
        const ulonglong2* wp = (const ulonglong2*)(
            whh + (size_t)(gg * 256 + k_unit) * H_DIM + cb * 32);
#pragma unroll
        for (int q = 0; q < 8; q++) {
            ulonglong2 v = wp[q];
            wr[gg][2 * q] = v.x;
            wr[gg][2 * q + 1] = v.y;
        }
    }

    for (int i = tid; i < 288; i += 256) { hsm[0][i] = 0.f; hsm[1][i] = 0.f; }

    uint32_t hbase = smem_u32(&hsm[0][0]);
    uint32_t pbase = smem_u32(&pre_s[0][0][0]);
    uint32_t sbase = smem_u32(&hstage[0][0]);
    uint32_t mb0 = smem_u32(&mbar_sm[0]);
    uint32_t mb1 = smem_u32(&mbar_sm[1]);

    if (tid == 0) {
        mbar_init(mb0, 1);
        mbar_init(mb1, 1);
        mbar_expect_tx(mb1, 896);    // step-0 sends (7 peers) land on mb1
    }

#define PRE_ISSUE(ck, ring)                                                   \
    do {                                                                      \
        _Pragma("unroll")                                                     \
        for (int pp = 0; pp < 2; pp++) {                                      \
            int idx = tid + pp * 256;                                         \
            int si_ = idx >> 5;                                               \
            int ga_ = (idx & 31) >> 3, l8_ = idx & 7;                         \
            int ss_ = (ck) * 16 + si_;                                        \
            int tt_ = dir ? (T_LEN - 1 - ss_) : ss_;                          \
            const float* src_ = pre + (size_t)tt_ * G_DIM + ga_ * 256 +       \
                                (int)rank * 32 + l8_ * 4;                     \
            uint32_t dst_ = pbase +                                           \
                (uint32_t)(((ring) * 16 + si_) * 144 + ga_ * 36 + l8_ * 4) * 4u; \
            cp_async16(dst_, src_);                                           \
        }                                                                     \
        asm volatile("cp.async.commit_group;" ::: "memory");                  \
    } while (0)

    PRE_ISSUE(0, 0);
    PRE_ISSUE(1, 1);

    // sender setup (warp 0 lanes 0-7, skipping self): this CTA's 32 h =
    // 128B contiguous at float-offset 36*rank in every CTA's hsm buffer.
    uint32_t dst_b0 = 0, dst_b1 = 0, mdst0 = 0, mdst1 = 0;
    bool sender = (warp == 0 && lane < 8 && (uint32_t)lane != rank);
    if (warp == 0 && lane < 8) {
        dst_b0 = mapa_u32(hbase + (uint32_t)(36 * rank) * 4u, (uint32_t)lane);
        dst_b1 = mapa_u32(hbase + (uint32_t)(288 + 36 * rank) * 4u, (uint32_t)lane);
        mdst0 = mapa_u32(mb0, (uint32_t)lane);
        mdst1 = mapa_u32(mb1, (uint32_t)lane);
    }

    __syncthreads();
    asm volatile("barrier.cluster.arrive.aligned;" ::: "memory");
    asm volatile("barrier.cluster.wait.aligned;" ::: "memory");

    float c = 0.f;                 // cell state at cb==0 lanes
    uint32_t par0 = 0, par1 = 0;

    for (int s = 0; s < T_LEN; s++) {
        int b = s & 1;
        int si = s & 15;
        int t = dir ? (T_LEN - 1 - s) : s;

        if (si == 0) {
            int c2 = (s >> 4) + 2;
            if (c2 < (T_LEN / 16)) {
                PRE_ISSUE(c2, c2 % 3);
                asm volatile("cp.async.wait_group 2;" ::: "memory");
            } else {
                asm volatile("cp.async.wait_group 0;" ::: "memory");
            }
            __syncthreads();
        }
        int buf = (s >> 4) % 3;

        // pre for gate cb of this unit (only cb<4 lanes add it)
        float p = (cb < 4) ? pre_s[buf][si][cb * 36 + unit] : 0.f;

        // wait until all 7 remote CTAs delivered h for this step
        if (s > 0) {
            if (b) { mbar_wait(mb1, par1); par1 ^= 1; }
            else   { mbar_wait(mb0, par0); par0 ^= 1; }
        }
        if (tid == 0) mbar_expect_tx(b ? mb1 : mb0, 896);

        // matvec: 4 gate rows x 32 cols; h from hsm[b] block cb
        const ulonglong2* h2 = (const ulonglong2*)(&hsm[b][cb * 36]);
        unsigned long long a0 = 0ull, a1 = 0ull, a2 = 0ull, a3 = 0ull;
#pragma unroll
        for (int q = 0; q < 8; q++) {
            ulonglong2 hv = h2[q];
            a0 = ffma2(wr[0][2 * q], hv.x, a0);
            a1 = ffma2(wr[1][2 * q], hv.x, a1);
            a2 = ffma2(wr[2][2 * q], hv.x, a2);
            a3 = ffma2(wr[3][2 * q], hv.x, a3);
            a0 = ffma2(wr[0][2 * q + 1], hv.y, a0);
            a1 = ffma2(wr[1][2 * q + 1], hv.y, a1);
            a2 = ffma2(wr[2][2 * q + 1], hv.y, a2);
            a3 = ffma2(wr[3][2 * q + 1], hv.y, a3);
        }
        float2 f0 = unpackf2(a0), f1 = unpackf2(a1);
        float2 f2 = unpackf2(a2), f3 = unpackf2(a3);
        float s0 = f0.x + f0.y, s1 = f1.x + f1.y;
        float s2 = f2.x + f2.y, s3 = f3.x + f3.y;

        if (cb == 0) s0 += p;
        else if (cb == 1) s1 += p;
        else if (cb == 2) s2 += p;
        else if (cb == 3) s3 += p;

#pragma unroll
        for (int mk = 1; mk < 8; mk <<= 1) {
            s0 += __shfl_xor_sync(0xffffffffu, s0, mk);
            s1 += __shfl_xor_sync(0xffffffffu, s1, mk);
            s2 += __shfl_xor_sync(0xffffffffu, s2, mk);
            s3 += __shfl_xor_sync(0xffffffffu, s3, mk);
        }

        // gates at cb==0 lanes (4 per warp), one unit each
        float h = 0.f;
        if (cb == 0) {
            float ii = sigmoidf_(s0);
            float ff = sigmoidf_(s1);
            float oo = sigmoidf_(s3);
            c = ff * c + ii * tanh_fast(s2);
            h = oo * tanh_fast(c);
            hstage[b ^ 1][unit] = h;
            hsm[b ^ 1][36 * (int)rank + unit] = h;   // self-delivery (local)
        }
        __syncthreads();   // hstage + local hsm staged; hsm[b] reads retired

        // warp 0 lanes 0-7 (minus self): ship 128B block to CTA 'lane'
        if (sender) {
            asm volatile("fence.proxy.async.shared::cta;" ::: "memory");
            uint32_t d = b ? dst_b0 : dst_b1;   // step-s output -> buffer b^1
            uint32_t m = b ? mdst0 : mdst1;
            bulk_s2cluster(d, sbase + (uint32_t)((b ^ 1) * 32) * 4u, 128u, m);
        }
        // hout store AFTER the barrier/send window: fully off critical path
        if (cb == 0) hout[(size_t)t * H_DIM + k_unit] = h;
    }

    // drain: final sends (step T-1, odd) targeted mb0; complete that phase
    mbar_wait(mb0, par0);
    asm volatile("barrier.cluster.arrive.aligned;" ::: "memory");
    asm volatile("barrier.cluster.wait.aligned;" ::: "memory");
#undef PRE_ISSUE
}

// ---------------- 3) emit: 16 timesteps per block, W_out SMEM-cached -------
__global__ __launch_bounds__(128) void emit_kernel(
    const float* __restrict__ Wout, const float* __restrict__ bout) {
    int t0 = blockIdx.x * 16;
    __shared__ float Wsm[L_TAGS * 512];     // 36 KB
    __shared__ float h[512];
    __shared__ float part[4][18];
    int tid = threadIdx.x;

    for (int i = tid; i < L_TAGS * 512; i += 128) Wsm[i] = Wout[i];

    for (int tl = 0; tl < 16; tl++) {
        int t = t0 + tl;
        __syncthreads();            // also covers Wsm on first iteration
        h[tid]       = g_h[0][(size_t)t * 256 + tid];
        h[tid + 128] = g_h[0][(size_t)t * 256 + 128 + tid];
        h[tid + 256] = g_h[1][(size_t)t * 256 + tid];
        h[tid + 384] = g_h[1][(size_t)t * 256 + 128 + tid];
        __syncthreads();

        if (tid < 72) {
            int jj = tid >> 2, q = tid & 3;
            const float* w = Wsm + jj * 512 + q * 128;
            const float* hh = h + q * 128;
            float a0 = 0.f, a1 = 0.f, a2 = 0.f, a3 = 0.f;
#pragma unroll
            for (int k = 0; k < 128; k += 4) {
                a0 += hh[k] * w[k];
                a1 += hh[k + 1] * w[k + 1];
                a2 += hh[k + 2] * w[k + 2];
                a3 += hh[k + 3] * w[k + 3];
            }
            part[q][jj] = (a0 + a1) + (a2 + a3);
        }
        __syncthreads();
        if (tid < 18)
            g_emit[(size_t)t * L_TAGS + tid] =
                part[0][tid] + part[1][tid] + part[2][tid] + part[3][tid] +
                bout[tid];
    }
}

// ---------------- 4) Viterbi + backtrack (one warp, R9 variant) -------------
__global__ void viterbi_kernel(const float* __restrict__ trans,
                               float* __restrict__ out, int write_score) {
    extern __shared__ unsigned char bp[];
    int j = threadIdx.x;
    bool act = (j < L_TAGS);

    float tcol[L_TAGS];
#pragma unroll
    for (int i = 0; i < L_TAGS; i++)
        tcol[i] = act ? trans[i * L_TAGS + j] : 0.f;

    float fv = act ? ((j == START_TAG) ? 0.f : NEGV) : -3.0e38f;
    float e = act ? g_emit[j] : 0.f;

    for (int t = 0; t < T_LEN; t++) {
        float e_next = (act && t + 1 < T_LEN)
                           ? g_emit[(size_t)(t + 1) * L_TAGS + j] : 0.f;
        // 6 independent chains of 3, merged ascending with strict >
        float bb[6];
        int aa[6];
#pragma unroll
        for (int ch = 0; ch < 6; ch++) { bb[ch] = -3.4e38f; aa[ch] = ch * 3; }
#pragma unroll
        for (int k = 0; k < 3; k++) {
#pragma unroll
            for (int ch = 0; ch < 6; ch++) {
                int i = ch * 3 + k;
                float sv = __shfl_sync(0xffffffffu, fv, i) + tcol[i];
                if (sv > bb[ch]) { bb[ch] = sv; aa[ch] = i; }
            }
        }
        float best = bb[0]; int arg = aa[0];
#pragma unroll
        for (int ch = 1; ch < 6; ch++)
            if (bb[ch] > best) { best = bb[ch]; arg = aa[ch]; }

        if (act) {
            bp[t * L_TAGS + j] = (unsigned char)arg;
            fv = best + e;
        }
        e = e_next;
    }

    float term = act ? (fv + trans[j * L_TAGS + STOP_TAG]) : -3.4e38f;
    int ai = j;
#pragma unroll
    for (int off = 16; off > 0; off >>= 1) {
        float ov = __shfl_xor_sync(0xffffffffu, term, off);
        int oi = __shfl_xor_sync(0xffffffffu, ai, off);
        if (ov > term || (ov == term && oi < ai)) { term = ov; ai = oi; }
    }

    if (j == 0) {
        if (write_score) out[0] = term;
        float* path = out + write_score;
        int tag = ai;
        for (int t = T_LEN - 1; t >= 0; t--) {
            path[t] = (float)tag;
            tag = bp[t * L_TAGS + tag];
        }
    }
}

// ---------------- launch ----------------------------------------------------
extern "C" void kernel_launch(void* const* d_in, const int* in_sizes, int n_in,
                              void* d_out, int out_size) {
    const int*   feats  = (const int*)d_in[0];
    const float* emb    = (const float*)d_in[1];
    const float* w_ih_f = (const float*)d_in[2];
    const float* w_hh_f = (const float*)d_in[3];
    const float* b_f    = (const float*)d_in[4];
    const float* w_ih_b = (const float*)d_in[5];
    const float* w_hh_b = (const float*)d_in[6];
    const float* b_b    = (const float*)d_in[7];
    const float* W_out  = (const float*)d_in[8];
    const float* b_out  = (const float*)d_in[9];
    const float* trans  = (const float*)d_in[10];

    dim3 gg(G_DIM / 64, T_LEN / 64, 2);
    gemm_pre_kernel<<<gg, 256>>>(feats, emb, w_ih_f, w_ih_b, b_f, b_b);

    lstm_cluster_kernel<<<16, 256>>>(w_hh_f, w_hh_b);

    emit_kernel<<<T_LEN / 16, 128>>>(W_out, b_out);

    int ws = (out_size > T_LEN) ? 1 : 0;   // layout: [path_score, path...]
    static int smem_set = 0;
    if (!smem_set) {
        cudaFuncSetAttribute(viterbi_kernel,
                             cudaFuncAttributeMaxDynamicSharedMemorySize,
                             T_LEN * L_TAGS + 1024);
        smem_set = 1;
    }
    viterbi_kernel<<<1, 32, T_LEN * L_TAGS>>>(trans, (float*)d_out, ws);
}